// round 3
// baseline (speedup 1.0000x reference)
#include <cuda_runtime.h>
#include <math.h>

// Problem constants (fixed shapes per reference)
#define N_ROWS 32768     // 32*32*32
#define DIM    256
#define KCODES 8192
#define NZ     (N_ROWS * DIM)   // 8388608

// GEMM-argmin tiling
#define BM 128
#define BN 128
#define BK 64
#define ZS_STRIDE 132    // padded row stride (floats) to avoid bank conflicts
#define SMEM_BYTES ((DIM * ZS_STRIDE + BK * ZS_STRIDE) * 4)  // 168960

__device__ float  g_esq[KCODES];
__device__ int    g_idx[N_ROWS];
__device__ int    g_cnt[KCODES];
__device__ double g_sse;

// ---------------------------------------------------------------------------
// Kernel 1: per-code squared norms
// ---------------------------------------------------------------------------
__global__ void k_esq(const float* __restrict__ cb) {
    int c = blockIdx.x * blockDim.x + threadIdx.x;
    if (c < KCODES) {
        const float4* p = (const float4*)(cb + (size_t)c * DIM);
        float s = 0.f;
#pragma unroll 8
        for (int i = 0; i < DIM / 4; ++i) {
            float4 v = p[i];
            s += v.x * v.x + v.y * v.y + v.z * v.z + v.w * v.w;
        }
        g_esq[c] = s;
    }
}

// ---------------------------------------------------------------------------
// Kernel 2: fused GEMM + argmin.
// dist(row, code) = ||e||^2 - 2 * <z_row, e_code>   (||z||^2 constant per row)
// Block: 256 threads (16x16), each thread owns an 8x8 microtile.
// Block tile: 128 rows x 128 codes, K streamed in chunks of 64.
// z tile (128 x 256) kept resident in smem (k-major, padded).
// ---------------------------------------------------------------------------
__global__ void __launch_bounds__(256, 1)
k_argmin(const float* __restrict__ z, const float* __restrict__ cb) {
    extern __shared__ float sm[];
    float* zs = sm;                         // [DIM][ZS_STRIDE] k-major
    float* es = sm + DIM * ZS_STRIDE;       // [BK][ZS_STRIDE]  k-major

    const int tid  = threadIdx.x;
    const int tx   = tid & 15;              // code group (8 codes)
    const int ty   = tid >> 4;              // row group (8 rows)
    const int row0 = blockIdx.x * BM;

    // Load + transpose the z tile: zs[k][row] = z[row0+row][k]
    // thread walks a fixed row with stride 32B (L1-line friendly)
    for (int t = tid; t < BM * (DIM / 4); t += 256) {
        int k4  = t >> 7;                   // 0..63
        int row = t & 127;
        float4 v = *(const float4*)(z + (size_t)(row0 + row) * DIM + k4 * 4);
        zs[(4 * k4 + 0) * ZS_STRIDE + row] = v.x;
        zs[(4 * k4 + 1) * ZS_STRIDE + row] = v.y;
        zs[(4 * k4 + 2) * ZS_STRIDE + row] = v.z;
        zs[(4 * k4 + 3) * ZS_STRIDE + row] = v.w;
    }

    float bestD[8];
    int   bestI[8];
#pragma unroll
    for (int i = 0; i < 8; ++i) { bestD[i] = INFINITY; bestI[i] = 0; }

    for (int c0 = 0; c0 < KCODES; c0 += BN) {
        float acc[8][8];
#pragma unroll
        for (int i = 0; i < 8; ++i)
#pragma unroll
            for (int j = 0; j < 8; ++j) acc[i][j] = 0.f;

        for (int kb = 0; kb < DIM; kb += BK) {
            __syncthreads();   // protect previous es contents
            // Load es tile: es[k][code] = cb[c0+code][kb+k], 128 codes x 64 k
            for (int t = tid; t < BN * (BK / 4); t += 256) {
                int k4   = t >> 7;          // 0..15
                int code = t & 127;
                float4 v = *(const float4*)(cb + (size_t)(c0 + code) * DIM + kb + k4 * 4);
                es[(4 * k4 + 0) * ZS_STRIDE + code] = v.x;
                es[(4 * k4 + 1) * ZS_STRIDE + code] = v.y;
                es[(4 * k4 + 2) * ZS_STRIDE + code] = v.z;
                es[(4 * k4 + 3) * ZS_STRIDE + code] = v.w;
            }
            __syncthreads();

#pragma unroll 8
            for (int k = 0; k < BK; ++k) {
                const float* zp = &zs[(size_t)(kb + k) * ZS_STRIDE + ty * 8];
                const float* ep = &es[(size_t)k * ZS_STRIDE + tx * 8];
                float zf[8], ef[8];
                *(float4*)&zf[0] = *(const float4*)(zp);
                *(float4*)&zf[4] = *(const float4*)(zp + 4);
                *(float4*)&ef[0] = *(const float4*)(ep);
                *(float4*)&ef[4] = *(const float4*)(ep + 4);
#pragma unroll
                for (int i = 0; i < 8; ++i)
#pragma unroll
                    for (int j = 0; j < 8; ++j)
                        acc[i][j] = fmaf(zf[i], ef[j], acc[i][j]);
            }
        }

        // Chunk epilogue: fold into running argmin (codes ascending -> strict <
        // keeps the lowest index on exact ties, matching jnp.argmin)
#pragma unroll
        for (int j = 0; j < 8; ++j) {
            int code = c0 + tx * 8 + j;
            float eq = g_esq[code];
#pragma unroll
            for (int i = 0; i < 8; ++i) {
                float d = eq - 2.0f * acc[i][j];
                if (d < bestD[i]) { bestD[i] = d; bestI[i] = code; }
            }
        }
    }

    // Cross-lane reduce over the 16 code-groups (width=16 keeps row groups apart)
#pragma unroll
    for (int off = 8; off > 0; off >>= 1) {
#pragma unroll
        for (int i = 0; i < 8; ++i) {
            float od = __shfl_down_sync(0xffffffffu, bestD[i], off, 16);
            int   oi = __shfl_down_sync(0xffffffffu, bestI[i], off, 16);
            if (od < bestD[i] || (od == bestD[i] && oi < bestI[i])) {
                bestD[i] = od; bestI[i] = oi;
            }
        }
    }
    if (tx == 0) {
#pragma unroll
        for (int i = 0; i < 8; ++i)
            g_idx[row0 + ty * 8 + i] = bestI[i];
    }
}

// ---------------------------------------------------------------------------
// Kernel 3: zero accumulators (graph replays must be deterministic)
// ---------------------------------------------------------------------------
__global__ void k_zero() {
    int t = blockIdx.x * blockDim.x + threadIdx.x;
    if (t < KCODES) g_cnt[t] = 0;
    if (t == 0) g_sse = 0.0;
}

// ---------------------------------------------------------------------------
// Kernel 4: gather z_q, write z_q_st = z_e + (z_q - z_e), indices (as float),
// accumulate SSE and histogram counts. One warp per row.
// ---------------------------------------------------------------------------
__global__ void k_gather(const float* __restrict__ z, const float* __restrict__ cb,
                         float* __restrict__ out) {
    int gwarp = (blockIdx.x * blockDim.x + threadIdx.x) >> 5;
    int lane  = threadIdx.x & 31;
    if (gwarp >= N_ROWS) return;
    int row = gwarp;
    int idx = g_idx[row];

    const float4* q  = (const float4*)(cb + (size_t)idx * DIM);
    const float4* ze = (const float4*)(z + (size_t)row * DIM);
    float4*       o  = (float4*)(out + (size_t)row * DIM);

    float s = 0.f;
#pragma unroll
    for (int i = 0; i < 2; ++i) {
        int c = lane + i * 32;
        float4 a = ze[c];
        float4 b = q[c];
        float4 r;
        r.x = a.x + (b.x - a.x);
        r.y = a.y + (b.y - a.y);
        r.z = a.z + (b.z - a.z);
        r.w = a.w + (b.w - a.w);
        float dx = a.x - b.x, dy = a.y - b.y, dz = a.z - b.z, dw = a.w - b.w;
        s += dx * dx + dy * dy + dz * dz + dw * dw;
        o[c] = r;
    }
#pragma unroll
    for (int off = 16; off > 0; off >>= 1)
        s += __shfl_down_sync(0xffffffffu, s, off);

    if (lane == 0) {
        atomicAdd(&g_sse, (double)s);
        atomicAdd(&g_cnt[idx], 1);
        out[NZ + row] = (float)idx;       // indices output (cast to float)
    }
}

// ---------------------------------------------------------------------------
// Kernel 5: loss + perplexity scalars
// ---------------------------------------------------------------------------
__global__ void k_final(float* __restrict__ out) {
    __shared__ float red[256];
    int t = threadIdx.x;
    float h = 0.f;
    for (int c = t; c < KCODES; c += 256) {
        float avg = (float)g_cnt[c] / (float)N_ROWS;
        h += avg * logf(avg + 1e-12f);
    }
    red[t] = h;
    __syncthreads();
    for (int s = 128; s > 0; s >>= 1) {
        if (t < s) red[t] += red[t + s];
        __syncthreads();
    }
    if (t == 0) {
        double mse = g_sse / (double)((size_t)N_ROWS * DIM);
        out[NZ + N_ROWS]     = (float)(1.25 * mse);   // codebook_loss + 0.25*commitment
        out[NZ + N_ROWS + 1] = expf(-red[0]);         // perplexity
    }
}

// ---------------------------------------------------------------------------
extern "C" void kernel_launch(void* const* d_in, const int* in_sizes, int n_in,
                              void* d_out, int out_size) {
    const float* z  = (const float*)d_in[0];   // z_e   [32,32,32,256]
    const float* cb = (const float*)d_in[1];   // codebook [8192,256]
    float* out = (float*)d_out;

    cudaFuncSetAttribute(k_argmin, cudaFuncAttributeMaxDynamicSharedMemorySize,
                         SMEM_BYTES);

    k_esq<<<KCODES / 256, 256>>>(cb);
    k_argmin<<<N_ROWS / BM, 256, SMEM_BYTES>>>(z, cb);
    k_zero<<<KCODES / 256, 256>>>();
    k_gather<<<(N_ROWS * 32) / 256, 256>>>(z, cb, out);
    k_final<<<1, 256>>>(out);
}

// round 5
// speedup vs baseline: 4.2915x; 4.2915x over previous
#include <cuda_runtime.h>
#include <cuda_bf16.h>
#include <math.h>
#include <stdint.h>

#define N_ROWS 32768
#define DIM    256
#define KCODES 8192
#define NZ     (N_ROWS * DIM)

#define CAP      192
#define MARGIN_F 0.25f

// SMEM: A = 8 k-chunks x (128 rows x 32 dim bf16, SW128) = 65536 B
//       B = 4 stages  x (128 codes x 32 dim bf16, SW128) = 32768 B
#define SM_A 0
#define SM_B 65536
#define SMEM_TOTAL 98304
#define NCHUNK_I 512         // 64 c-chunks x 8 k-chunks

__device__ __nv_bfloat16 g_zbf[N_ROWS * DIM];
__device__ __nv_bfloat16 g_cbbf[KCODES * DIM];
__device__ float  g_esq[KCODES];
__device__ float  g_bestAppx[N_ROWS];
__device__ int    g_ccnt[N_ROWS];
__device__ int    g_over[N_ROWS];
__device__ float  g_candD[(size_t)N_ROWS * CAP];
__device__ int    g_candC[(size_t)N_ROWS * CAP];
__device__ int    g_idx[N_ROWS];
__device__ int    g_cnt[KCODES];
__device__ double g_sse;

// ---------------------------------------------------------------------------
__device__ __forceinline__ uint32_t smem_u32(const void* p) {
    uint32_t a;
    asm("{ .reg .u64 t; cvta.to.shared.u64 t, %1; cvt.u32.u64 %0, t; }"
        : "=r"(a) : "l"(p));
    return a;
}

#define SW128(x) ((x) ^ (((x) >> 3) & 0x70))

#define CP_ASYNC16(dst, src) \
    asm volatile("cp.async.cg.shared.global [%0], [%1], 16;" \
                 :: "r"((uint32_t)(dst)), "l"(src) : "memory")
#define CP_COMMIT() asm volatile("cp.async.commit_group;" ::: "memory")
#define CP_WAIT(n)  asm volatile("cp.async.wait_group %0;" :: "n"(n) : "memory")

__device__ __forceinline__ void ldsm4(uint32_t* r, uint32_t addr) {
    asm volatile("ldmatrix.sync.aligned.m8n8.x4.shared.b16 {%0,%1,%2,%3}, [%4];"
                 : "=r"(r[0]), "=r"(r[1]), "=r"(r[2]), "=r"(r[3]) : "r"(addr));
}

__device__ __forceinline__ void mma16816(float* d, const uint32_t* a, const uint32_t* b) {
    asm volatile(
        "mma.sync.aligned.m16n8k16.row.col.f32.bf16.bf16.f32 "
        "{%0,%1,%2,%3}, {%4,%5,%6,%7}, {%8,%9}, {%0,%1,%2,%3};"
        : "+f"(d[0]), "+f"(d[1]), "+f"(d[2]), "+f"(d[3])
        : "r"(a[0]), "r"(a[1]), "r"(a[2]), "r"(a[3]), "r"(b[0]), "r"(b[1]));
}

__device__ __forceinline__ void cand_insert(int row, int col, float d) {
    int p = atomicAdd(&g_ccnt[row], 1);
    if (p < CAP) {
        g_candD[(size_t)row * CAP + p] = d;
        g_candC[(size_t)row * CAP + p] = col;
    } else {
        g_over[row] = 1;
    }
}

// ---------------------------------------------------------------------------
__global__ void k_cvt(const float* __restrict__ s, __nv_bfloat16* __restrict__ d, int n8) {
    int t = blockIdx.x * blockDim.x + threadIdx.x;
    if (t < n8) {
        float4 a = ((const float4*)s)[t * 2];
        float4 b = ((const float4*)s)[t * 2 + 1];
        __nv_bfloat162 p0 = __floats2bfloat162_rn(a.x, a.y);
        __nv_bfloat162 p1 = __floats2bfloat162_rn(a.z, a.w);
        __nv_bfloat162 p2 = __floats2bfloat162_rn(b.x, b.y);
        __nv_bfloat162 p3 = __floats2bfloat162_rn(b.z, b.w);
        uint4 o;
        o.x = *(uint32_t*)&p0; o.y = *(uint32_t*)&p1;
        o.z = *(uint32_t*)&p2; o.w = *(uint32_t*)&p3;
        ((uint4*)d)[t] = o;
    }
}

__global__ void k_esq(const float* __restrict__ cb) {
    int c = blockIdx.x * blockDim.x + threadIdx.x;
    if (c < KCODES) {
        const float4* p = (const float4*)(cb + (size_t)c * DIM);
        float s = 0.f;
#pragma unroll 8
        for (int i = 0; i < DIM / 4; ++i) {
            float4 v = p[i];
            s += v.x * v.x + v.y * v.y + v.z * v.z + v.w * v.w;
        }
        g_esq[c] = s;
    }
}

__global__ void k_zero0() {
    int t = blockIdx.x * blockDim.x + threadIdx.x;
    if (t < N_ROWS) { g_ccnt[t] = 0; g_over[t] = 0; }
}

// ---------------------------------------------------------------------------
// GEMM-argmin: 256 CTAs x 256 thr. Warp w owns rows row0 + w*16 .. +15 across
// ALL 8192 codes (warp tile 16x128). bf16 HMMA, fp32 accum.
// ---------------------------------------------------------------------------
__global__ void __launch_bounds__(256, 2)
k_gemm() {
    extern __shared__ char smem[];
    const uint32_t sb = smem_u32(smem);
    const int tid  = threadIdx.x;
    const int wid  = tid >> 5;
    const int lane = tid & 31;
    const int g    = lane >> 2;
    const int tg   = lane & 3;
    const int m0   = wid * 16;
    const int row0 = blockIdx.x * 128;

    // ---- A prologue: 128 rows x 256 dims, 8 k-chunks, SW128 ---------------
#pragma unroll
    for (int t = 0; t < 16; ++t) {
        int idx = tid + t * 256;                 // 0..4095
        int kb  = idx >> 9;
        int r   = (idx >> 2) & 127;
        int c16 = idx & 3;
        uint32_t off = (uint32_t)r * 64 + c16 * 16;
        CP_ASYNC16(sb + SM_A + kb * 8192 + SW128(off),
                   g_zbf + (size_t)(row0 + r) * DIM + kb * 32 + c16 * 8);
    }
    CP_COMMIT();

    // ---- B prologue: stages 0..2 ------------------------------------------
#pragma unroll
    for (int s = 0; s < 3; ++s) {
#pragma unroll
        for (int t = 0; t < 2; ++t) {
            int idx = tid + t * 256;             // 0..511
            int n   = idx >> 2;
            int c16 = idx & 3;
            uint32_t off = (uint32_t)n * 64 + c16 * 16;
            // chunk s: cc = s>>3 = 0, kb = s
            CP_ASYNC16(sb + SM_B + s * 8192 + SW128(off),
                       g_cbbf + (size_t)n * DIM + s * 32 + c16 * 8);
        }
        CP_COMMIT();
    }
    CP_WAIT(3);          // A complete (3 B stages may be pending)
    __syncthreads();

    const int rowA = row0 + m0 + g;
    const int rowB = rowA + 8;
    float bestA = INFINITY, thrA = INFINITY;
    float bestB = INFINITY, thrB = INFINITY;

    float acc[16][4];

    // ldmatrix lane address components (constant per thread)
    const uint32_t a_r  = (uint32_t)(m0 + (lane & 15)) * 64;
    const uint32_t a_k  = ((lane >> 4) * 8) * 2;
    const uint32_t b_n  = (uint32_t)((lane & 7) + ((lane >> 4) & 1) * 8) * 64;
    const uint32_t b_k  = (((lane >> 3) & 1) * 8) * 2;

    for (int i = 0; i < NCHUNK_I; ++i) {
        const int cc = i >> 3;
        const int kb = i & 7;

        // wait for chunk i's B stage; tail-aware
        if (i <= NCHUNK_I - 3)      CP_WAIT(2);
        else if (i == NCHUNK_I - 2) CP_WAIT(1);
        else                        CP_WAIT(0);
        __syncthreads();

        // prefetch chunk i+3
        if (i + 3 < NCHUNK_I) {
            const int ci = i + 3;
            const int pcc = ci >> 3, pkb = ci & 7;
            const uint32_t bbase = sb + SM_B + (ci & 3) * 8192;
#pragma unroll
            for (int t = 0; t < 2; ++t) {
                int idx = tid + t * 256;
                int n   = idx >> 2;
                int c16 = idx & 3;
                uint32_t off = (uint32_t)n * 64 + c16 * 16;
                CP_ASYNC16(bbase + SW128(off),
                           g_cbbf + (size_t)(pcc * 128 + n) * DIM + pkb * 32 + c16 * 8);
            }
        }
        CP_COMMIT();   // keep group count in lockstep even on tail

        if (kb == 0) {
#pragma unroll
            for (int nt = 0; nt < 16; ++nt)
#pragma unroll
                for (int j = 0; j < 4; ++j) acc[nt][j] = 0.f;
        }

        const uint32_t abase = sb + SM_A + kb * 8192;
        const uint32_t bbase = sb + SM_B + (i & 3) * 8192;

#pragma unroll
        for (int s = 0; s < 2; ++s) {
            uint32_t a[4];
            {
                uint32_t off = a_r + (uint32_t)(s * 32) + a_k;
                ldsm4(a, abase + SW128(off));
            }
#pragma unroll
            for (int p = 0; p < 8; ++p) {
                uint32_t b[4];
                uint32_t off = b_n + (uint32_t)(p * 1024) + (uint32_t)(s * 32) + b_k;
                ldsm4(b, bbase + SW128(off));
                mma16816(acc[2 * p],     a, b);
                mma16816(acc[2 * p + 1], a, b + 2);
            }
        }

        if (kb == 7) {
            // epilogue: fold 128 codes into per-row candidate machinery
            const int c0 = cc * 128;
#pragma unroll
            for (int nt = 0; nt < 16; ++nt) {
                const int cb0  = nt * 8 + 2 * tg;
                const int colg = c0 + cb0;
                const float e0 = __ldg(&g_esq[colg]);
                const float e1 = __ldg(&g_esq[colg + 1]);
                float d0 = fmaf(acc[nt][0], -2.f, e0);
                float d1 = fmaf(acc[nt][1], -2.f, e1);
                float d2 = fmaf(acc[nt][2], -2.f, e0);
                float d3 = fmaf(acc[nt][3], -2.f, e1);
                if (d0 < thrA) { cand_insert(rowA, colg,     d0); if (d0 < bestA) { bestA = d0; thrA = d0 + MARGIN_F; } }
                if (d1 < thrA) { cand_insert(rowA, colg + 1, d1); if (d1 < bestA) { bestA = d1; thrA = d1 + MARGIN_F; } }
                if (d2 < thrB) { cand_insert(rowB, colg,     d2); if (d2 < bestB) { bestB = d2; thrB = d2 + MARGIN_F; } }
                if (d3 < thrB) { cand_insert(rowB, colg + 1, d3); if (d3 < bestB) { bestB = d3; thrB = d3 + MARGIN_F; } }
            }
        }
    }

    // quad-reduce lane bests (lanes g*4..g*4+3 hold same rows)
#pragma unroll
    for (int m = 1; m <= 2; m <<= 1) {
        float oA = __shfl_xor_sync(0xffffffffu, bestA, m);
        float oB = __shfl_xor_sync(0xffffffffu, bestB, m);
        bestA = fminf(bestA, oA);
        bestB = fminf(bestB, oB);
    }
    if (tg == 0) {
        g_bestAppx[rowA] = bestA;
        g_bestAppx[rowB] = bestB;
    }
}

// ---------------------------------------------------------------------------
__device__ __forceinline__ float exact_d(const float* z, const float* cb, int row, int c) {
    const float4* zp = (const float4*)(z + (size_t)row * DIM);
    const float4* ep = (const float4*)(cb + (size_t)c * DIM);
    float s0 = 0.f, s1 = 0.f, s2 = 0.f, s3 = 0.f;
#pragma unroll 16
    for (int q = 0; q < 64; ++q) {
        float4 a = zp[q], b = ep[q];
        s0 = fmaf(a.x, b.x, s0);
        s1 = fmaf(a.y, b.y, s1);
        s2 = fmaf(a.z, b.z, s2);
        s3 = fmaf(a.w, b.w, s3);
    }
    return fmaf(-2.0f, (s0 + s1) + (s2 + s3), __ldg(&g_esq[c]));
}

__global__ void k_rescore(const float* __restrict__ z, const float* __restrict__ cb) {
    const int gw   = (blockIdx.x * blockDim.x + threadIdx.x) >> 5;
    const int lane = threadIdx.x & 31;
    if (gw >= N_ROWS) return;
    const int row = gw;

    float bd = INFINITY;
    int   bi = 0x7fffffff;

    if (!g_over[row]) {
        const float thr = g_bestAppx[row] + MARGIN_F;
        const int   n   = min(g_ccnt[row], CAP);
        const size_t cbase = (size_t)row * CAP;
        if (n <= 32) {
            float ad = (lane < n) ? g_candD[cbase + lane] : INFINITY;
            unsigned m = __ballot_sync(0xffffffffu, ad <= thr);
            if (__popc(m) == 1) {
                if (ad <= thr) g_idx[row] = g_candC[cbase + lane];
                return;
            }
            if (ad <= thr) {
                int c = g_candC[cbase + lane];
                bd = exact_d(z, cb, row, c);
                bi = c;
            }
        } else {
            for (int k = lane; k < n; k += 32) {
                if (g_candD[cbase + k] <= thr) {
                    int c = g_candC[cbase + k];
                    float d = exact_d(z, cb, row, c);
                    if (d < bd || (d == bd && c < bi)) { bd = d; bi = c; }
                }
            }
        }
    } else {
        for (int c = lane; c < KCODES; c += 32) {
            float d = exact_d(z, cb, row, c);
            if (d < bd || (d == bd && c < bi)) { bd = d; bi = c; }
        }
    }

#pragma unroll
    for (int off = 16; off > 0; off >>= 1) {
        float od = __shfl_down_sync(0xffffffffu, bd, off);
        int   oi = __shfl_down_sync(0xffffffffu, bi, off);
        if (od < bd || (od == bd && oi < bi)) { bd = od; bi = oi; }
    }
    if (lane == 0) g_idx[row] = bi;
}

// ---------------------------------------------------------------------------
__global__ void k_zero() {
    int t = blockIdx.x * blockDim.x + threadIdx.x;
    if (t < KCODES) g_cnt[t] = 0;
    if (t == 0) g_sse = 0.0;
}

__global__ void k_gather(const float* __restrict__ z, const float* __restrict__ cb,
                         float* __restrict__ out) {
    int gwarp = (blockIdx.x * blockDim.x + threadIdx.x) >> 5;
    int lane  = threadIdx.x & 31;
    if (gwarp >= N_ROWS) return;
    int row = gwarp;
    int idx = g_idx[row];

    const float4* q  = (const float4*)(cb + (size_t)idx * DIM);
    const float4* ze = (const float4*)(z + (size_t)row * DIM);
    float4*       o  = (float4*)(out + (size_t)row * DIM);

    float s = 0.f;
#pragma unroll
    for (int i = 0; i < 2; ++i) {
        int c = lane + i * 32;
        float4 a = ze[c];
        float4 b = q[c];
        float4 r;
        r.x = a.x + (b.x - a.x);
        r.y = a.y + (b.y - a.y);
        r.z = a.z + (b.z - a.z);
        r.w = a.w + (b.w - a.w);
        float dx = a.x - b.x, dy = a.y - b.y, dz = a.z - b.z, dw = a.w - b.w;
        s += dx * dx + dy * dy + dz * dz + dw * dw;
        o[c] = r;
    }
#pragma unroll
    for (int off = 16; off > 0; off >>= 1)
        s += __shfl_down_sync(0xffffffffu, s, off);

    if (lane == 0) {
        atomicAdd(&g_sse, (double)s);
        atomicAdd(&g_cnt[idx], 1);
        out[NZ + row] = (float)idx;
    }
}

__global__ void k_final(float* __restrict__ out) {
    __shared__ float red[256];
    int t = threadIdx.x;
    float h = 0.f;
    for (int c = t; c < KCODES; c += 256) {
        float avg = (float)g_cnt[c] / (float)N_ROWS;
        h += avg * logf(avg + 1e-12f);
    }
    red[t] = h;
    __syncthreads();
    for (int s = 128; s > 0; s >>= 1) {
        if (t < s) red[t] += red[t + s];
        __syncthreads();
    }
    if (t == 0) {
        double mse = g_sse / (double)((size_t)N_ROWS * DIM);
        out[NZ + N_ROWS]     = (float)(1.25 * mse);
        out[NZ + N_ROWS + 1] = expf(-red[0]);
    }
}

// ---------------------------------------------------------------------------
extern "C" void kernel_launch(void* const* d_in, const int* in_sizes, int n_in,
                              void* d_out, int out_size) {
    const float* z  = (const float*)d_in[0];
    const float* cb = (const float*)d_in[1];
    float* out = (float*)d_out;

    __nv_bfloat16 *zbf, *cbbf;
    cudaGetSymbolAddress((void**)&zbf,  g_zbf);
    cudaGetSymbolAddress((void**)&cbbf, g_cbbf);

    cudaFuncSetAttribute(k_gemm, cudaFuncAttributeMaxDynamicSharedMemorySize, SMEM_TOTAL);

    k_cvt<<<NZ / 8 / 256, 256>>>(z, zbf, NZ / 8);
    k_cvt<<<KCODES * DIM / 8 / 256, 256>>>(cb, cbbf, KCODES * DIM / 8);
    k_esq<<<KCODES / 256, 256>>>(cb);
    k_zero0<<<N_ROWS / 256, 256>>>();
    k_gemm<<<256, 256, SMEM_TOTAL>>>();
    k_rescore<<<4096, 256>>>(z, cb);
    k_zero<<<KCODES / 256, 256>>>();
    k_gather<<<(N_ROWS * 32) / 256, 256>>>(z, cb, out);
    k_final<<<1, 256>>>(out);
}

// round 6
// speedup vs baseline: 4.6276x; 1.0783x over previous
#include <cuda_runtime.h>
#include <cuda_bf16.h>
#include <math.h>
#include <stdint.h>

#define N_ROWS 32768
#define DIM    256
#define KCODES 8192
#define NZ     (N_ROWS * DIM)

#define CAP      192
#define MARGIN_F 0.25f

// SMEM: A = 4 k-chunks x (128 rows x 64 dim bf16, 128B rows SW128) = 65536 B
//       B = 2 stages  x (128 codes x 64 dim bf16, 128B rows SW128) = 32768 B
#define SM_A 0
#define SM_B 65536
#define SMEM_TOTAL 98304
#define NITER 256            // 64 c-chunks x 4 k-chunks (k=64 each)

__device__ __nv_bfloat16 g_zbf[N_ROWS * DIM];
__device__ __nv_bfloat16 g_cbbf[KCODES * DIM];
__device__ float  g_esq[KCODES];
__device__ float  g_bestAppx[N_ROWS];
__device__ int    g_ccnt[N_ROWS];
__device__ int    g_over[N_ROWS];
__device__ float  g_candD[(size_t)N_ROWS * CAP];
__device__ int    g_candC[(size_t)N_ROWS * CAP];
__device__ int    g_cnt[KCODES];
__device__ double g_sse;

// ---------------------------------------------------------------------------
__device__ __forceinline__ uint32_t smem_u32(const void* p) {
    uint32_t a;
    asm("{ .reg .u64 t; cvta.to.shared.u64 t, %1; cvt.u32.u64 %0, t; }"
        : "=r"(a) : "l"(p));
    return a;
}

#define SW128(x) ((x) ^ (((x) >> 3) & 0x70))

#define CP_ASYNC16(dst, src) \
    asm volatile("cp.async.cg.shared.global [%0], [%1], 16;" \
                 :: "r"((uint32_t)(dst)), "l"(src) : "memory")
#define CP_COMMIT() asm volatile("cp.async.commit_group;" ::: "memory")
#define CP_WAIT0()  asm volatile("cp.async.wait_group 0;" ::: "memory")

__device__ __forceinline__ void ldsm4(uint32_t* r, uint32_t addr) {
    asm volatile("ldmatrix.sync.aligned.m8n8.x4.shared.b16 {%0,%1,%2,%3}, [%4];"
                 : "=r"(r[0]), "=r"(r[1]), "=r"(r[2]), "=r"(r[3]) : "r"(addr));
}

__device__ __forceinline__ void mma16816(float* d, const uint32_t* a, const uint32_t* b) {
    asm volatile(
        "mma.sync.aligned.m16n8k16.row.col.f32.bf16.bf16.f32 "
        "{%0,%1,%2,%3}, {%4,%5,%6,%7}, {%8,%9}, {%0,%1,%2,%3};"
        : "+f"(d[0]), "+f"(d[1]), "+f"(d[2]), "+f"(d[3])
        : "r"(a[0]), "r"(a[1]), "r"(a[2]), "r"(a[3]), "r"(b[0]), "r"(b[1]));
}

__device__ __forceinline__ void cand_insert(int row, int col, float d) {
    int p = atomicAdd(&g_ccnt[row], 1);
    if (p < CAP) {
        g_candD[(size_t)row * CAP + p] = d;
        g_candC[(size_t)row * CAP + p] = col;
    } else {
        g_over[row] = 1;
    }
}

// ---------------------------------------------------------------------------
__global__ void k_cvt(const float* __restrict__ s, __nv_bfloat16* __restrict__ d, int n8) {
    int t = blockIdx.x * blockDim.x + threadIdx.x;
    if (t < n8) {
        float4 a = ((const float4*)s)[t * 2];
        float4 b = ((const float4*)s)[t * 2 + 1];
        __nv_bfloat162 p0 = __floats2bfloat162_rn(a.x, a.y);
        __nv_bfloat162 p1 = __floats2bfloat162_rn(a.z, a.w);
        __nv_bfloat162 p2 = __floats2bfloat162_rn(b.x, b.y);
        __nv_bfloat162 p3 = __floats2bfloat162_rn(b.z, b.w);
        uint4 o;
        o.x = *(uint32_t*)&p0; o.y = *(uint32_t*)&p1;
        o.z = *(uint32_t*)&p2; o.w = *(uint32_t*)&p3;
        ((uint4*)d)[t] = o;
    }
}

// esq + all per-replay zeroing (runs before gemm/rescore in stream order)
__global__ void k_esq(const float* __restrict__ cb) {
    int c = blockIdx.x * blockDim.x + threadIdx.x;   // 0..8191
    if (c < KCODES) {
        const float4* p = (const float4*)(cb + (size_t)c * DIM);
        float s = 0.f;
#pragma unroll 8
        for (int i = 0; i < DIM / 4; ++i) {
            float4 v = p[i];
            s += v.x * v.x + v.y * v.y + v.z * v.z + v.w * v.w;
        }
        g_esq[c] = s;
        g_cnt[c] = 0;
#pragma unroll
        for (int r = 0; r < 4; ++r) {
            g_ccnt[c * 4 + r] = 0;
            g_over[c * 4 + r] = 0;
        }
        if (c == 0) g_sse = 0.0;
    }
}

// ---------------------------------------------------------------------------
// GEMM-argmin: 256 CTAs x 256 thr (8 warps). Warp w owns rows row0+w*16..+15
// across all 8192 codes. bf16 HMMA fp32 accum. k-chunks of 64, 2-stage B.
// ---------------------------------------------------------------------------
__global__ void __launch_bounds__(256, 2)
k_gemm() {
    extern __shared__ char smem[];
    const uint32_t sb = smem_u32(smem);
    const int tid  = threadIdx.x;
    const int wid  = tid >> 5;
    const int lane = tid & 31;
    const int g    = lane >> 2;
    const int tg   = lane & 3;
    const int m0   = wid * 16;
    const int row0 = blockIdx.x * 128;

    // ---- A prologue: 4 chunks x (128 rows x 64 dims), 128B rows, SW128 ----
#pragma unroll
    for (int t = 0; t < 16; ++t) {
        int idx = tid + t * 256;                 // 0..4095
        int kb  = idx >> 10;                     // 0..3
        int j   = idx & 1023;
        int r   = j >> 3;                        // 0..127
        int c8  = j & 7;                         // 0..7 (16B units)
        uint32_t off = (uint32_t)r * 128 + c8 * 16;
        CP_ASYNC16(sb + SM_A + kb * 16384 + SW128(off),
                   g_zbf + (size_t)(row0 + r) * DIM + kb * 64 + c8 * 8);
    }
    CP_COMMIT();

    // ---- B stage 0 (iter 0: cc=0, kb=0) -----------------------------------
#pragma unroll
    for (int t = 0; t < 4; ++t) {
        int idx = tid + t * 256;                 // 0..1023
        int n   = idx >> 3;
        int c8  = idx & 7;
        uint32_t off = (uint32_t)n * 128 + c8 * 16;
        CP_ASYNC16(sb + SM_B + SW128(off),
                   g_cbbf + (size_t)n * DIM + c8 * 8);
    }
    CP_COMMIT();

    const int rowA = row0 + m0 + g;
    const int rowB = rowA + 8;
    float bestA = INFINITY, thrA = INFINITY;
    float bestB = INFINITY, thrB = INFINITY;

    float acc[16][4];

    // ldmatrix lane address components
    const uint32_t a_base = (uint32_t)(m0 + (lane & 15)) * 128 + ((lane >> 4) * 16);
    const uint32_t b_base = (uint32_t)((lane & 7) + ((lane >> 4) & 1) * 8) * 128
                          + (((lane >> 3) & 1) * 16);

    for (int i = 0; i < NITER; ++i) {
        const int cc = i >> 2;
        const int kb = i & 3;

        CP_WAIT0();
        __syncthreads();

        // prefetch next B stage
        if (i + 1 < NITER) {
            const int ci  = i + 1;
            const int pcc = ci >> 2, pkb = ci & 3;
            const uint32_t bb = sb + SM_B + (ci & 1) * 16384;
#pragma unroll
            for (int t = 0; t < 4; ++t) {
                int idx = tid + t * 256;
                int n   = idx >> 3;
                int c8  = idx & 7;
                uint32_t off = (uint32_t)n * 128 + c8 * 16;
                CP_ASYNC16(bb + SW128(off),
                           g_cbbf + (size_t)(pcc * 128 + n) * DIM + pkb * 64 + c8 * 8);
            }
            CP_COMMIT();
        }

        if (kb == 0) {
#pragma unroll
            for (int nt = 0; nt < 16; ++nt)
#pragma unroll
                for (int j = 0; j < 4; ++j) acc[nt][j] = 0.f;
        }

        const uint32_t abase = sb + SM_A + kb * 16384;
        const uint32_t bbase = sb + SM_B + (i & 1) * 16384;

#pragma unroll
        for (int s = 0; s < 4; ++s) {
            uint32_t a[4];
            ldsm4(a, abase + SW128(a_base + (uint32_t)(s * 32)));
#pragma unroll
            for (int p = 0; p < 8; ++p) {
                uint32_t b[4];
                ldsm4(b, bbase + SW128(b_base + (uint32_t)(p * 2048) + (uint32_t)(s * 32)));
                mma16816(acc[2 * p],     a, b);
                mma16816(acc[2 * p + 1], a, b + 2);
            }
        }

        if (kb == 3) {
            const int c0 = cc * 128;
#pragma unroll
            for (int nt = 0; nt < 16; ++nt) {
                const int colg = c0 + nt * 8 + 2 * tg;
                const float e0 = __ldg(&g_esq[colg]);
                const float e1 = __ldg(&g_esq[colg + 1]);
                float d0 = fmaf(acc[nt][0], -2.f, e0);
                float d1 = fmaf(acc[nt][1], -2.f, e1);
                float d2 = fmaf(acc[nt][2], -2.f, e0);
                float d3 = fmaf(acc[nt][3], -2.f, e1);
                if (d0 < thrA) { cand_insert(rowA, colg,     d0); if (d0 < bestA) { bestA = d0; thrA = d0 + MARGIN_F; } }
                if (d1 < thrA) { cand_insert(rowA, colg + 1, d1); if (d1 < bestA) { bestA = d1; thrA = d1 + MARGIN_F; } }
                if (d2 < thrB) { cand_insert(rowB, colg,     d2); if (d2 < bestB) { bestB = d2; thrB = d2 + MARGIN_F; } }
                if (d3 < thrB) { cand_insert(rowB, colg + 1, d3); if (d3 < bestB) { bestB = d3; thrB = d3 + MARGIN_F; } }
            }
        }
    }

    // quad-reduce per-lane bests (lanes tg=0..3 share each row)
#pragma unroll
    for (int m = 1; m <= 2; m <<= 1) {
        bestA = fminf(bestA, __shfl_xor_sync(0xffffffffu, bestA, m));
        bestB = fminf(bestB, __shfl_xor_sync(0xffffffffu, bestB, m));
    }
    if (tg == 0) {
        g_bestAppx[rowA] = bestA;
        g_bestAppx[rowB] = bestB;
    }
}

// ---------------------------------------------------------------------------
__device__ __forceinline__ float exact_d(const float* z, const float* cb, int row, int c) {
    const float4* zp = (const float4*)(z + (size_t)row * DIM);
    const float4* ep = (const float4*)(cb + (size_t)c * DIM);
    float s0 = 0.f, s1 = 0.f, s2 = 0.f, s3 = 0.f;
#pragma unroll 16
    for (int q = 0; q < 64; ++q) {
        float4 a = zp[q], b = ep[q];
        s0 = fmaf(a.x, b.x, s0);
        s1 = fmaf(a.y, b.y, s1);
        s2 = fmaf(a.z, b.z, s2);
        s3 = fmaf(a.w, b.w, s3);
    }
    return fmaf(-2.0f, (s0 + s1) + (s2 + s3), __ldg(&g_esq[c]));
}

// ---------------------------------------------------------------------------
// Rescore + gather fused: one warp per row. Picks exact argmin among
// survivors, then writes z_q_st, index, and accumulates SSE + histogram.
// ---------------------------------------------------------------------------
__global__ void k_rescore_gather(const float* __restrict__ z,
                                 const float* __restrict__ cb,
                                 float* __restrict__ out) {
    const int gw   = (blockIdx.x * blockDim.x + threadIdx.x) >> 5;
    const int lane = threadIdx.x & 31;
    if (gw >= N_ROWS) return;
    const int row = gw;

    float bd = INFINITY;
    int   bi = 0x7fffffff;
    bool  done = false;

    if (!g_over[row]) {
        const float thr = g_bestAppx[row] + MARGIN_F;
        const int   n   = min(g_ccnt[row], CAP);
        const size_t cbase = (size_t)row * CAP;
        if (n <= 32) {
            float ad = (lane < n) ? g_candD[cbase + lane] : INFINITY;
            int   c  = (lane < n) ? g_candC[cbase + lane] : 0x7fffffff;
            unsigned m = __ballot_sync(0xffffffffu, ad <= thr);
            if (__popc(m) == 1) {
                bi = __shfl_sync(0xffffffffu, c, __ffs(m) - 1);
                done = true;
            } else if (ad <= thr) {
                bd = exact_d(z, cb, row, c);
                bi = c;
            }
        } else {
            for (int k = lane; k < n; k += 32) {
                if (g_candD[cbase + k] <= thr) {
                    int c = g_candC[cbase + k];
                    float d = exact_d(z, cb, row, c);
                    if (d < bd || (d == bd && c < bi)) { bd = d; bi = c; }
                }
            }
        }
    } else {
        for (int c = lane; c < KCODES; c += 32) {
            float d = exact_d(z, cb, row, c);
            if (d < bd || (d == bd && c < bi)) { bd = d; bi = c; }
        }
    }

    if (!done) {
#pragma unroll
        for (int off = 16; off > 0; off >>= 1) {
            float od = __shfl_xor_sync(0xffffffffu, bd, off);
            int   oi = __shfl_xor_sync(0xffffffffu, bi, off);
            if (od < bd || (od == bd && oi < bi)) { bd = od; bi = oi; }
        }
    }
    const int idx = bi;    // identical on all lanes

    // -------- gather / outputs --------
    const float4* q  = (const float4*)(cb + (size_t)idx * DIM);
    const float4* ze = (const float4*)(z + (size_t)row * DIM);
    float4*       o  = (float4*)(out + (size_t)row * DIM);

    float s = 0.f;
#pragma unroll
    for (int i = 0; i < 2; ++i) {
        int c = lane + i * 32;
        float4 a = ze[c];
        float4 b = q[c];
        float4 r;
        r.x = a.x + (b.x - a.x);
        r.y = a.y + (b.y - a.y);
        r.z = a.z + (b.z - a.z);
        r.w = a.w + (b.w - a.w);
        float dx = a.x - b.x, dy = a.y - b.y, dz = a.z - b.z, dw = a.w - b.w;
        s += dx * dx + dy * dy + dz * dz + dw * dw;
        o[c] = r;
    }
#pragma unroll
    for (int off = 16; off > 0; off >>= 1)
        s += __shfl_down_sync(0xffffffffu, s, off);

    if (lane == 0) {
        atomicAdd(&g_sse, (double)s);
        atomicAdd(&g_cnt[idx], 1);
        out[NZ + row] = (float)idx;
    }
}

__global__ void k_final(float* __restrict__ out) {
    __shared__ float red[256];
    int t = threadIdx.x;
    float h = 0.f;
    for (int c = t; c < KCODES; c += 256) {
        float avg = (float)g_cnt[c] / (float)N_ROWS;
        h += avg * logf(avg + 1e-12f);
    }
    red[t] = h;
    __syncthreads();
    for (int s = 128; s > 0; s >>= 1) {
        if (t < s) red[t] += red[t + s];
        __syncthreads();
    }
    if (t == 0) {
        double mse = g_sse / (double)((size_t)N_ROWS * DIM);
        out[NZ + N_ROWS]     = (float)(1.25 * mse);
        out[NZ + N_ROWS + 1] = expf(-red[0]);
    }
}

// ---------------------------------------------------------------------------
extern "C" void kernel_launch(void* const* d_in, const int* in_sizes, int n_in,
                              void* d_out, int out_size) {
    const float* z  = (const float*)d_in[0];
    const float* cb = (const float*)d_in[1];
    float* out = (float*)d_out;

    __nv_bfloat16 *zbf, *cbbf;
    cudaGetSymbolAddress((void**)&zbf,  g_zbf);
    cudaGetSymbolAddress((void**)&cbbf, g_cbbf);

    cudaFuncSetAttribute(k_gemm, cudaFuncAttributeMaxDynamicSharedMemorySize, SMEM_TOTAL);

    k_cvt<<<NZ / 8 / 256, 256>>>(z, zbf, NZ / 8);                 // 1
    k_cvt<<<KCODES * DIM / 8 / 256, 256>>>(cb, cbbf, KCODES * DIM / 8); // 2
    k_esq<<<KCODES / 256, 256>>>(cb);                             // 3 (+zeroing)
    k_gemm<<<256, 256, SMEM_TOTAL>>>();                           // 4 <- ncu slot
    k_rescore_gather<<<4096, 256>>>(z, cb, out);                  // 5
    k_final<<<1, 256>>>(out);                                     // 6
}